// round 3
// baseline (speedup 1.0000x reference)
#include <cuda_runtime.h>

#define BASIS 1e-10f
#define TPB 256

__global__ void transition_prob_kernel(
    const float* __restrict__ adstock,
    const float* __restrict__ mu,
    const float* __restrict__ beta,
    const float* __restrict__ init_prob,
    const float* __restrict__ click_prob,
    float* __restrict__ out,
    int days,
    long long total /* b * dur */)
{
    __shared__ float s[TPB * 9];
    const int tid = threadIdx.x;
    const long long idx = (long long)blockIdx.x * TPB + tid;
    const int dur = days - 1;

    if (idx < total) {
        const long long b = idx / dur;
        const int d = (int)(idx - b * (long long)dur);

        const float* ap = adstock + b * 3LL * days + (d + 1);
        const float a0 = __ldg(ap);
        const float a1 = __ldg(ap + days);
        const float a2 = __ldg(ap + 2 * days);

        const float b0 = __ldg(beta + 0), b1 = __ldg(beta + 1), b2 = __ldg(beta + 2);
        const float b3 = __ldg(beta + 3), b4 = __ldg(beta + 4), b5 = __ldg(beta + 5);
        const float b6 = __ldg(beta + 6), b7 = __ldg(beta + 7), b8 = __ldg(beta + 8);
        const float m0 = __ldg(mu + 0), m1 = __ldg(mu + 1), m2 = __ldg(mu + 2);

        // O_beta[k] = sum_c adstock[b,c,d+1] * beta[c*3 + (k-1)], k=1..3
        const float O1 = fmaf(a0, b0, fmaf(a1, b3, a2 * b6));
        const float O2 = fmaf(a0, b1, fmaf(a1, b4, a2 * b7));
        const float O3 = fmaf(a0, b2, fmaf(a1, b5, a2 * b8));

        // num[0][0] = exp(-inf) = 0
        const float n01 = expf(m0 + O1);
        const float n10 = expf(m1 + O2);
        const float n11 = expf(m2 + O3);

        const float id0 = 1.0f / (1.0f + n01);
        const float id1 = 1.0f / (1.0f + n10 + n11);

        float* sp = s + tid * 9;  // stride 9 coprime with 32 -> conflict-free
        sp[0] = fmaxf(id0,       BASIS);  // Q[0][0] = 1/den0
        sp[1] = fmaxf(n01 * id0, BASIS);  // Q[0][1] = upper[0]
        sp[2] = BASIS;                    // Q[0][2] = 0 -> basis
        sp[3] = fmaxf(n10 * id1, BASIS);  // Q[1][0] = lower[0]
        sp[4] = fmaxf(id1,       BASIS);  // Q[1][1] = 1/den1
        sp[5] = fmaxf(n11 * id1, BASIS);  // Q[1][2] = upper[1]
        sp[6] = BASIS;                    // Q[2][0]
        sp[7] = BASIS;                    // Q[2][1] = lower[1] = 0 -> basis
        sp[8] = 1.0f;                     // Q[2][2]
    }
    __syncthreads();

    // Coalesced float4 copy-out of this block's 9*TPB floats
    const long long blockBase = (long long)blockIdx.x * TPB;  // first (b,d) idx
    long long nElems = total - blockBase;
    if (nElems > TPB) nElems = TPB;
    if (nElems > 0) {
        const long long outBase = blockBase * 9;
        const int nFloats = (int)(nElems * 9);
        if ((nFloats & 3) == 0) {
            const float4* s4 = (const float4*)s;
            float4* o4 = (float4*)(out + outBase);
            const int n4 = nFloats >> 2;
            for (int i = tid; i < n4; i += TPB) o4[i] = s4[i];
        } else {
            for (int i = tid; i < nFloats; i += TPB) out[outBase + i] = s[i];
        }
    }

    if (idx == 0) {
        const float ip = __ldg(init_prob);
        const float cp = __ldg(click_prob);
        out[total * 9]     = 1.0f / (1.0f + expf(-ip));
        out[total * 9 + 1] = 1.0f / (1.0f + expf(-cp));
    }
}

extern "C" void kernel_launch(void* const* d_in, const int* in_sizes, int n_in,
                              void* d_out, int out_size)
{
    const float* adstock    = (const float*)d_in[0];
    const float* mu         = (const float*)d_in[1];
    const float* beta       = (const float*)d_in[2];
    const float* init_prob  = (const float*)d_in[3];
    const float* click_prob = (const float*)d_in[4];
    float* out = (float*)d_out;

    const long long in0 = (long long)in_sizes[0];        // b * 3 * days
    const long long q   = ((long long)out_size - 2) / 9; // b * (days-1)
    const long long bd  = in0 / 3;                       // b * days
    const long long b   = bd - q;                        // b
    const int days      = (int)(bd / b);

    const long long total = q;
    const long long blocks = (total + TPB - 1) / TPB;
    transition_prob_kernel<<<(unsigned int)blocks, TPB>>>(
        adstock, mu, beta, init_prob, click_prob, out, days, total);
}

// round 4
// speedup vs baseline: 1.0945x; 1.0945x over previous
#include <cuda_runtime.h>

#define BASIS 1e-10f
#define TPB 256

// c_p[0..8] = beta * log2(e)   (row-major [campaign][k])
// c_p[9..11] = mu * log2(e)
__constant__ float c_p[12];
__device__ float g_tmp[12];

__device__ __forceinline__ float ex2_approx(float x) {
    float y; asm("ex2.approx.ftz.f32 %0, %1;" : "=f"(y) : "f"(x)); return y;
}
__device__ __forceinline__ float rcp_approx(float x) {
    float y; asm("rcp.approx.ftz.f32 %0, %1;" : "=f"(y) : "f"(x)); return y;
}

__global__ void setup_kernel(const float* __restrict__ mu,
                             const float* __restrict__ beta,
                             const float* __restrict__ init_prob,
                             const float* __restrict__ click_prob,
                             float* __restrict__ out,
                             long long total)
{
    if (threadIdx.x == 0) {
        const float L2E = 1.4426950408889634f;
        #pragma unroll
        for (int i = 0; i < 9; i++) g_tmp[i] = beta[i] * L2E;
        #pragma unroll
        for (int i = 0; i < 3; i++) g_tmp[9 + i] = mu[i] * L2E;
        out[total * 9]     = 1.0f / (1.0f + __expf(-init_prob[0]));
        out[total * 9 + 1] = 1.0f / (1.0f + __expf(-click_prob[0]));
    }
}

__global__ void transition_prob_kernel(
    const float* __restrict__ adstock,
    float* __restrict__ out,
    int days, int dur)
{
    __shared__ float s[TPB * 9];
    const int tid = threadIdx.x;
    const int dBase = blockIdx.x * TPB;
    const int d = dBase + tid;
    const long long row = blockIdx.y;

    if (d < dur) {
        const float* ap = adstock + row * 3LL * days + (d + 1);
        const float a0 = __ldg(ap);
        const float a1 = __ldg(ap + days);
        const float a2 = __ldg(ap + 2 * days);

        // log2-domain: t_k = (mu[k] + sum_c a_c * beta[c,k]) * log2e, all consts in c[]
        const float t1 = fmaf(a0, c_p[0], fmaf(a1, c_p[3], fmaf(a2, c_p[6], c_p[9])));
        const float t2 = fmaf(a0, c_p[1], fmaf(a1, c_p[4], fmaf(a2, c_p[7], c_p[10])));
        const float t3 = fmaf(a0, c_p[2], fmaf(a1, c_p[5], fmaf(a2, c_p[8], c_p[11])));

        const float n01 = ex2_approx(t1);   // num[0][1]
        const float n10 = ex2_approx(t2);   // num[1][0]
        const float n11 = ex2_approx(t3);   // num[1][1]

        const float id0 = rcp_approx(1.0f + n01);
        const float id1 = rcp_approx(1.0f + n10 + n11);

        float* sp = s + tid * 9;            // stride 9 coprime with 32 -> conflict-free
        sp[0] = fmaxf(id0,       BASIS);    // Q[0][0]
        sp[1] = fmaxf(n01 * id0, BASIS);    // Q[0][1]
        sp[2] = BASIS;                      // Q[0][2]
        sp[3] = fmaxf(n10 * id1, BASIS);    // Q[1][0]
        sp[4] = fmaxf(id1,       BASIS);    // Q[1][1]
        sp[5] = fmaxf(n11 * id1, BASIS);    // Q[1][2]
        sp[6] = BASIS;                      // Q[2][0]
        sp[7] = BASIS;                      // Q[2][1]
        sp[8] = 1.0f;                       // Q[2][2]
    }
    __syncthreads();

    int nElems = dur - dBase;
    if (nElems > TPB) nElems = TPB;
    const long long outBase = (row * dur + dBase) * 9LL;
    const int nFloats = nElems * 9;
    if (((outBase & 3) | (nFloats & 3)) == 0) {
        const float4* s4 = (const float4*)s;
        float4* o4 = (float4*)(out + outBase);
        const int n4 = nFloats >> 2;
        #pragma unroll
        for (int i = tid; i < n4; i += TPB) o4[i] = s4[i];
    } else {
        for (int i = tid; i < nFloats; i += TPB) out[outBase + i] = s[i];
    }
}

extern "C" void kernel_launch(void* const* d_in, const int* in_sizes, int n_in,
                              void* d_out, int out_size)
{
    const float* adstock    = (const float*)d_in[0];
    const float* mu         = (const float*)d_in[1];
    const float* beta       = (const float*)d_in[2];
    const float* init_prob  = (const float*)d_in[3];
    const float* click_prob = (const float*)d_in[4];
    float* out = (float*)d_out;

    const long long in0 = (long long)in_sizes[0];        // b * 3 * days
    const long long q   = ((long long)out_size - 2) / 9; // b * (days-1)
    const long long bd  = in0 / 3;                       // b * days
    const long long b   = bd - q;                        // b
    const int days      = (int)(bd / b);
    const int dur       = days - 1;

    setup_kernel<<<1, 32>>>(mu, beta, init_prob, click_prob, out, q);

    void* tmp_addr = nullptr;
    cudaGetSymbolAddress(&tmp_addr, g_tmp);
    cudaMemcpyToSymbolAsync(c_p, tmp_addr, 12 * sizeof(float), 0,
                            cudaMemcpyDeviceToDevice, 0);

    dim3 grid((unsigned)((dur + TPB - 1) / TPB), (unsigned)b);
    transition_prob_kernel<<<grid, TPB>>>(adstock, out, days, dur);
}